// round 8
// baseline (speedup 1.0000x reference)
#include <cuda_runtime.h>
#include <math.h>

#define T_TOK 8192
#define D_DIM 4096
#define KS 4
#define N_SLOTS 128
#define TOPK 1024
#define MAX_ENTRIES 4096   // TOPK * KS worst case into one slot
#define NCHUNK 8           // 512-col chunks per token row

// ---------------- scratch (static device globals; no allocation) ----------
__device__ float g_phh[T_TOK * NCHUNK];   // per-(token,chunk) sum h*h
__device__ float g_phw[T_TOK * NCHUNK];   // per-(token,chunk) sum h*W
__device__ int   g_slot_cnt[N_SLOTS];
__device__ int   g_slot_tokens[N_SLOTS * MAX_ENTRIES];

// ---------------------------------------------------------------------------
// Kernel 1: barrier-free partial sums for importance.
// Block = 1 token (8 warps); warp w owns columns [w*512, (w+1)*512).
// Each lane: 4 float4 of h (__ldcs, streaming) + 4 float4 of W (__ldg,
// L1-resident), batched 2+2 to keep regs ~32 for 64-warp/SM occupancy.
// Warp shfl-reduce, lane 0 writes the two partials. No smem, no barriers.
// ---------------------------------------------------------------------------
__global__ void importance_partial_kernel(const float* __restrict__ h,
                                          const float* __restrict__ W) {
    const int t = blockIdx.x;
    const int wid = threadIdx.x >> 5;       // chunk 0..7
    const int lane = threadIdx.x & 31;

    const float4* __restrict__ hr =
        reinterpret_cast<const float4*>(h + (size_t)t * D_DIM) + wid * 128;
    const float4* __restrict__ wr =
        reinterpret_cast<const float4*>(W) + wid * 128;

    float hh = 0.f, hw = 0.f;
#pragma unroll
    for (int qq = 0; qq < 4; qq += 2) {
        float4 a0 = __ldcs(&hr[lane + 32 * qq]);
        float4 a1 = __ldcs(&hr[lane + 32 * (qq + 1)]);
        float4 w0 = __ldg(&wr[lane + 32 * qq]);
        float4 w1 = __ldg(&wr[lane + 32 * (qq + 1)]);
        hh += a0.x * a0.x + a0.y * a0.y + a0.z * a0.z + a0.w * a0.w;
        hw += a0.x * w0.x + a0.y * w0.y + a0.z * w0.z + a0.w * w0.w;
        hh += a1.x * a1.x + a1.y * a1.y + a1.z * a1.z + a1.w * a1.w;
        hw += a1.x * w1.x + a1.y * w1.y + a1.z * w1.z + a1.w * w1.w;
    }
#pragma unroll
    for (int off = 16; off; off >>= 1) {
        hh += __shfl_xor_sync(0xFFFFFFFFu, hh, off);
        hw += __shfl_xor_sync(0xFFFFFFFFu, hw, off);
    }
    if (lane == 0) {
        g_phh[t * NCHUNK + wid] = hh;
        g_phw[t * NCHUNK + wid] = hw;
    }
}

// ---------------------------------------------------------------------------
// Kernel 2: finalize importance (folded in) + exact top-1024 selection
// (R1 core verbatim — fastest measured) + per-slot list build.
// Ties broken toward lowest index to match jax.lax.top_k's selected SET.
// ---------------------------------------------------------------------------
__global__ void select_kernel(const int* __restrict__ slot_indices,
                              const float* __restrict__ attn,
                              const float* __restrict__ b) {
    __shared__ unsigned int su[T_TOK];   // 32 KB sortable keys
    __shared__ int hist[256];
    __shared__ int s_bucket, s_k, s_cnt;
    __shared__ int s_slot_cnt[N_SLOTS];

    int tid = threadIdx.x;
    float bv = b[0];

    // finalize importance for 8 tokens/thread, convert to sortable key
#pragma unroll
    for (int i = 0; i < 8; i++) {
        int t = tid + i * 1024;
        const float4* ph = reinterpret_cast<const float4*>(&g_phh[t * NCHUNK]);
        const float4* pw = reinterpret_cast<const float4*>(&g_phw[t * NCHUNK]);
        float4 h0 = ph[0], h1 = ph[1];
        float4 w0 = pw[0], w1 = pw[1];
        float hh = (h0.x + h0.y) + (h0.z + h0.w) + (h1.x + h1.y) + (h1.z + h1.w);
        float hw = (w0.x + w0.y) + (w0.z + w0.w) + (w1.x + w1.y) + (w1.z + w1.w);
        float mag = sqrtf(hh);
        float4 a4 = *reinterpret_cast<const float4*>(attn + t * 4);
        float ent = -(a4.x * logf(a4.x + 1e-8f) + a4.y * logf(a4.y + 1e-8f) +
                      a4.z * logf(a4.z + 1e-8f) + a4.w * logf(a4.w + 1e-8f));
        float surprise = ent * (1.0f / 1.3862943611198906f);   // / log(4)
        float learned = 1.0f / (1.0f + expf(-(hw + bv)));
        float imp = mag * (1.0f + surprise) + learned;

        unsigned int u = __float_as_uint(imp);
        u ^= (u & 0x80000000u) ? 0xFFFFFFFFu : 0x80000000u;
        su[t] = u;
    }
    __syncthreads();

    // 4-pass 8-bit radix select for the value v of the TOPK-th largest key
    unsigned int prefix = 0, kmask = 0;
    int k = TOPK;
    for (int shift = 24; shift >= 0; shift -= 8) {
        if (tid < 256) hist[tid] = 0;
        __syncthreads();
#pragma unroll
        for (int i = 0; i < 8; i++) {
            int t = tid + i * 1024;
            unsigned int u = su[t];
            if ((u & kmask) == prefix) atomicAdd(&hist[(u >> shift) & 255], 1);
        }
        __syncthreads();
        if (tid == 0) {
            int cum = 0, bsel = 0;
            for (int bb = 255; bb >= 0; bb--) {
                cum += hist[bb];
                if (cum >= k) { bsel = bb; s_k = k - (cum - hist[bb]); break; }
            }
            s_bucket = bsel;
        }
        __syncthreads();
        prefix |= ((unsigned int)s_bucket) << shift;
        kmask  |= 0xFFu << shift;
        k = s_k;
        __syncthreads();
    }
    unsigned int v = prefix;
    int r = k;   // need r elements among keys == v, taken at smallest indices

    // count ties
    if (tid == 0) s_cnt = 0;
    __syncthreads();
    {
        int c = 0;
#pragma unroll
        for (int i = 0; i < 8; i++) { int t = tid + i * 1024; c += (su[t] == v); }
        atomicAdd(&s_cnt, c);
    }
    __syncthreads();
    int m = s_cnt;

    // binary search index threshold X: smallest X with |{t < X : key==v}| >= r
    int X = T_TOK;
    if (r < m) {
        int lo = 0, hi = T_TOK;
        while (lo < hi) {
            int mid = (lo + hi) >> 1;
            __syncthreads();
            if (tid == 0) s_cnt = 0;
            __syncthreads();
            int c = 0;
#pragma unroll
            for (int i = 0; i < 8; i++) {
                int t = tid + i * 1024;
                c += (t < mid && su[t] == v);
            }
            atomicAdd(&s_cnt, c);
            __syncthreads();
            int got = s_cnt;
            __syncthreads();
            if (got >= r) hi = mid; else lo = mid + 1;
        }
        X = lo;
    }

    // build per-slot token lists
    if (tid < N_SLOTS) s_slot_cnt[tid] = 0;
    __syncthreads();
#pragma unroll
    for (int i = 0; i < 8; i++) {
        int t = tid + i * 1024;
        unsigned int u = su[t];
        if (u > v || (u == v && t < X)) {
            int4 s4 = *reinterpret_cast<const int4*>(slot_indices + t * KS);
            int s;
            s = s4.x; g_slot_tokens[s * MAX_ENTRIES + atomicAdd(&s_slot_cnt[s], 1)] = t;
            s = s4.y; g_slot_tokens[s * MAX_ENTRIES + atomicAdd(&s_slot_cnt[s], 1)] = t;
            s = s4.z; g_slot_tokens[s * MAX_ENTRIES + atomicAdd(&s_slot_cnt[s], 1)] = t;
            s = s4.w; g_slot_tokens[s * MAX_ENTRIES + atomicAdd(&s_slot_cnt[s], 1)] = t;
        }
    }
    __syncthreads();
    if (tid < N_SLOTS) g_slot_cnt[tid] = s_slot_cnt[tid];
}

// ---------------------------------------------------------------------------
// Kernel 3: per-slot gather-sum, mean, EMA write (R1 version verbatim).
// One block per (slot, 512-col chunk). 4-way unrolled gather.
// ---------------------------------------------------------------------------
__global__ void aggregate_kernel(const float* __restrict__ h,
                                 const float* __restrict__ mem,
                                 float* __restrict__ out) {
    int slot = blockIdx.y;
    int col4 = blockIdx.x * 128 + threadIdx.x;   // float4 index (0..1023)
    int cnt = g_slot_cnt[slot];

    const float4* cur_row = reinterpret_cast<const float4*>(mem + (size_t)slot * D_DIM);
    float4 cur = cur_row[col4];
    float4 res = cur;

    if (cnt > 0) {
        const int* toks = &g_slot_tokens[slot * MAX_ENTRIES];
        float4 a0 = {0, 0, 0, 0}, a1 = {0, 0, 0, 0}, a2 = {0, 0, 0, 0}, a3 = {0, 0, 0, 0};
        int i = 0;
        for (; i + 3 < cnt; i += 4) {
            int t0 = toks[i], t1 = toks[i + 1], t2 = toks[i + 2], t3 = toks[i + 3];
            float4 v0 = reinterpret_cast<const float4*>(h + (size_t)t0 * D_DIM)[col4];
            float4 v1 = reinterpret_cast<const float4*>(h + (size_t)t1 * D_DIM)[col4];
            float4 v2 = reinterpret_cast<const float4*>(h + (size_t)t2 * D_DIM)[col4];
            float4 v3 = reinterpret_cast<const float4*>(h + (size_t)t3 * D_DIM)[col4];
            a0.x += v0.x; a0.y += v0.y; a0.z += v0.z; a0.w += v0.w;
            a1.x += v1.x; a1.y += v1.y; a1.z += v1.z; a1.w += v1.w;
            a2.x += v2.x; a2.y += v2.y; a2.z += v2.z; a2.w += v2.w;
            a3.x += v3.x; a3.y += v3.y; a3.z += v3.z; a3.w += v3.w;
        }
        for (; i < cnt; i++) {
            int t0 = toks[i];
            float4 v0 = reinterpret_cast<const float4*>(h + (size_t)t0 * D_DIM)[col4];
            a0.x += v0.x; a0.y += v0.y; a0.z += v0.z; a0.w += v0.w;
        }
        float inv = 1.0f / (float)cnt;
        float sx = (a0.x + a1.x) + (a2.x + a3.x);
        float sy = (a0.y + a1.y) + (a2.y + a3.y);
        float sz = (a0.z + a1.z) + (a2.z + a3.z);
        float sw = (a0.w + a1.w) + (a2.w + a3.w);
        res.x = 0.1f * (sx * inv) + 0.9f * cur.x;
        res.y = 0.1f * (sy * inv) + 0.9f * cur.y;
        res.z = 0.1f * (sz * inv) + 0.9f * cur.z;
        res.w = 0.1f * (sw * inv) + 0.9f * cur.w;
    }
    reinterpret_cast<float4*>(out)[slot * (D_DIM / 4) + col4] = res;
}

// ---------------------------------------------------------------------------
extern "C" void kernel_launch(void* const* d_in, const int* in_sizes, int n_in,
                              void* d_out, int out_size) {
    const float* hidden = (const float*)d_in[0];   // [8192, 4096]
    const float* attn   = (const float*)d_in[1];   // [8192, 4]
    const float* memory = (const float*)d_in[2];   // [1, 128, 4096]
    const float* W      = (const float*)d_in[3];   // [1, 4096]
    const float* b      = (const float*)d_in[4];   // [1]
    const int*   slots  = (const int*)d_in[5];     // [8192, 4]
    float* out = (float*)d_out;                    // [1, 128, 4096]

    importance_partial_kernel<<<T_TOK, 256>>>(hidden, W);
    select_kernel<<<1, 1024>>>(slots, attn, b);
    aggregate_kernel<<<dim3(8, N_SLOTS), 128>>>(hidden, memory, out);
}

// round 10
// speedup vs baseline: 1.0537x; 1.0537x over previous
#include <cuda_runtime.h>
#include <math.h>

#define T_TOK 8192
#define D_DIM 4096
#define KS 4
#define N_SLOTS 128
#define TOPK 1024
#define MAX_ENTRIES 4096   // TOPK * KS worst case into one slot
#define NCHUNK 8           // 512-col chunks per token row

// ---------------- scratch (static device globals; no allocation) ----------
__device__ float g_phh[T_TOK * NCHUNK];   // per-(token,chunk) sum h*h
__device__ float g_phw[T_TOK * NCHUNK];   // per-(token,chunk) sum h*W
__device__ int   g_slot_cnt[N_SLOTS];
__device__ int   g_slot_tokens[N_SLOTS * MAX_ENTRIES];

// ---------------------------------------------------------------------------
// Kernel 1: barrier-free partial sums for importance (best measured: 25.5us).
// Block = 1 token (8 warps); warp w owns columns [w*512, (w+1)*512).
// __launch_bounds__(256,7) trims regs for 56-warp/SM occupancy.
// Warp shfl-reduce, lane 0 writes partials with __stcg (read once later).
// ---------------------------------------------------------------------------
__global__ void __launch_bounds__(256, 7)
importance_partial_kernel(const float* __restrict__ h,
                          const float* __restrict__ W) {
    const int t = blockIdx.x;
    const int wid = threadIdx.x >> 5;       // chunk 0..7
    const int lane = threadIdx.x & 31;

    const float4* __restrict__ hr =
        reinterpret_cast<const float4*>(h + (size_t)t * D_DIM) + wid * 128;
    const float4* __restrict__ wr =
        reinterpret_cast<const float4*>(W) + wid * 128;

    float hh = 0.f, hw = 0.f;
#pragma unroll
    for (int qq = 0; qq < 4; qq += 2) {
        float4 a0 = __ldcs(&hr[lane + 32 * qq]);
        float4 a1 = __ldcs(&hr[lane + 32 * (qq + 1)]);
        float4 w0 = __ldg(&wr[lane + 32 * qq]);
        float4 w1 = __ldg(&wr[lane + 32 * (qq + 1)]);
        hh += a0.x * a0.x + a0.y * a0.y + a0.z * a0.z + a0.w * a0.w;
        hw += a0.x * w0.x + a0.y * w0.y + a0.z * w0.z + a0.w * w0.w;
        hh += a1.x * a1.x + a1.y * a1.y + a1.z * a1.z + a1.w * a1.w;
        hw += a1.x * w1.x + a1.y * w1.y + a1.z * w1.z + a1.w * w1.w;
    }
#pragma unroll
    for (int off = 16; off; off >>= 1) {
        hh += __shfl_xor_sync(0xFFFFFFFFu, hh, off);
        hw += __shfl_xor_sync(0xFFFFFFFFu, hw, off);
    }
    if (lane == 0) {
        __stcg(&g_phh[t * NCHUNK + wid], hh);
        __stcg(&g_phw[t * NCHUNK + wid], hw);
    }
}

// ---------------------------------------------------------------------------
// Kernel 2: finalize importance (folded, MUFU intrinsics — ~3x cheaper than
// polynomial logf on this single SM) + exact top-1024 selection (R1 core
// verbatim — fastest measured across 4 attempts) + per-slot list build.
// Ties broken toward lowest index to match jax.lax.top_k's selected SET.
// ---------------------------------------------------------------------------
__global__ void select_kernel(const int* __restrict__ slot_indices,
                              const float* __restrict__ attn,
                              const float* __restrict__ b) {
    __shared__ unsigned int su[T_TOK];   // 32 KB sortable keys
    __shared__ int hist[256];
    __shared__ int s_bucket, s_k, s_cnt;
    __shared__ int s_slot_cnt[N_SLOTS];

    int tid = threadIdx.x;
    float bv = b[0];

    // finalize importance for 8 tokens/thread, convert to sortable key
#pragma unroll
    for (int i = 0; i < 8; i++) {
        int t = tid + i * 1024;
        const float4* ph = reinterpret_cast<const float4*>(&g_phh[t * NCHUNK]);
        const float4* pw = reinterpret_cast<const float4*>(&g_phw[t * NCHUNK]);
        float4 h0 = ph[0], h1 = ph[1];
        float4 w0 = pw[0], w1 = pw[1];
        float hh = (h0.x + h0.y) + (h0.z + h0.w) + (h1.x + h1.y) + (h1.z + h1.w);
        float hw = (w0.x + w0.y) + (w0.z + w0.w) + (w1.x + w1.y) + (w1.z + w1.w);
        float mag = sqrtf(hh);
        float4 a4 = *reinterpret_cast<const float4*>(attn + t * 4);
        float ent = -(a4.x * __logf(a4.x + 1e-8f) + a4.y * __logf(a4.y + 1e-8f) +
                      a4.z * __logf(a4.z + 1e-8f) + a4.w * __logf(a4.w + 1e-8f));
        float surprise = ent * (1.0f / 1.3862943611198906f);   // / log(4)
        float learned = 1.0f / (1.0f + __expf(-(hw + bv)));
        float imp = mag * (1.0f + surprise) + learned;

        unsigned int u = __float_as_uint(imp);
        u ^= (u & 0x80000000u) ? 0xFFFFFFFFu : 0x80000000u;
        su[t] = u;
    }
    __syncthreads();

    // 4-pass 8-bit radix select for the value v of the TOPK-th largest key
    unsigned int prefix = 0, kmask = 0;
    int k = TOPK;
    for (int shift = 24; shift >= 0; shift -= 8) {
        if (tid < 256) hist[tid] = 0;
        __syncthreads();
#pragma unroll
        for (int i = 0; i < 8; i++) {
            int t = tid + i * 1024;
            unsigned int u = su[t];
            if ((u & kmask) == prefix) atomicAdd(&hist[(u >> shift) & 255], 1);
        }
        __syncthreads();
        if (tid == 0) {
            int cum = 0, bsel = 0;
            for (int bb = 255; bb >= 0; bb--) {
                cum += hist[bb];
                if (cum >= k) { bsel = bb; s_k = k - (cum - hist[bb]); break; }
            }
            s_bucket = bsel;
        }
        __syncthreads();
        prefix |= ((unsigned int)s_bucket) << shift;
        kmask  |= 0xFFu << shift;
        k = s_k;
        __syncthreads();
    }
    unsigned int v = prefix;
    int r = k;   // need r elements among keys == v, taken at smallest indices

    // count ties
    if (tid == 0) s_cnt = 0;
    __syncthreads();
    {
        int c = 0;
#pragma unroll
        for (int i = 0; i < 8; i++) { int t = tid + i * 1024; c += (su[t] == v); }
        atomicAdd(&s_cnt, c);
    }
    __syncthreads();
    int m = s_cnt;

    // binary search index threshold X: smallest X with |{t < X : key==v}| >= r
    int X = T_TOK;
    if (r < m) {
        int lo = 0, hi = T_TOK;
        while (lo < hi) {
            int mid = (lo + hi) >> 1;
            __syncthreads();
            if (tid == 0) s_cnt = 0;
            __syncthreads();
            int c = 0;
#pragma unroll
            for (int i = 0; i < 8; i++) {
                int t = tid + i * 1024;
                c += (t < mid && su[t] == v);
            }
            atomicAdd(&s_cnt, c);
            __syncthreads();
            int got = s_cnt;
            __syncthreads();
            if (got >= r) hi = mid; else lo = mid + 1;
        }
        X = lo;
    }

    // build per-slot token lists
    if (tid < N_SLOTS) s_slot_cnt[tid] = 0;
    __syncthreads();
#pragma unroll
    for (int i = 0; i < 8; i++) {
        int t = tid + i * 1024;
        unsigned int u = su[t];
        if (u > v || (u == v && t < X)) {
            int4 s4 = *reinterpret_cast<const int4*>(slot_indices + t * KS);
            int s;
            s = s4.x; g_slot_tokens[s * MAX_ENTRIES + atomicAdd(&s_slot_cnt[s], 1)] = t;
            s = s4.y; g_slot_tokens[s * MAX_ENTRIES + atomicAdd(&s_slot_cnt[s], 1)] = t;
            s = s4.z; g_slot_tokens[s * MAX_ENTRIES + atomicAdd(&s_slot_cnt[s], 1)] = t;
            s = s4.w; g_slot_tokens[s * MAX_ENTRIES + atomicAdd(&s_slot_cnt[s], 1)] = t;
        }
    }
    __syncthreads();
    if (tid < N_SLOTS) g_slot_cnt[tid] = s_slot_cnt[tid];
}

// ---------------------------------------------------------------------------
// Kernel 3: per-slot gather-sum, mean, EMA write (R1 version verbatim).
// One block per (slot, 512-col chunk). 4-way unrolled gather.
// ---------------------------------------------------------------------------
__global__ void aggregate_kernel(const float* __restrict__ h,
                                 const float* __restrict__ mem,
                                 float* __restrict__ out) {
    int slot = blockIdx.y;
    int col4 = blockIdx.x * 128 + threadIdx.x;   // float4 index (0..1023)
    int cnt = g_slot_cnt[slot];

    const float4* cur_row = reinterpret_cast<const float4*>(mem + (size_t)slot * D_DIM);
    float4 cur = cur_row[col4];
    float4 res = cur;

    if (cnt > 0) {
        const int* toks = &g_slot_tokens[slot * MAX_ENTRIES];
        float4 a0 = {0, 0, 0, 0}, a1 = {0, 0, 0, 0}, a2 = {0, 0, 0, 0}, a3 = {0, 0, 0, 0};
        int i = 0;
        for (; i + 3 < cnt; i += 4) {
            int t0 = toks[i], t1 = toks[i + 1], t2 = toks[i + 2], t3 = toks[i + 3];
            float4 v0 = reinterpret_cast<const float4*>(h + (size_t)t0 * D_DIM)[col4];
            float4 v1 = reinterpret_cast<const float4*>(h + (size_t)t1 * D_DIM)[col4];
            float4 v2 = reinterpret_cast<const float4*>(h + (size_t)t2 * D_DIM)[col4];
            float4 v3 = reinterpret_cast<const float4*>(h + (size_t)t3 * D_DIM)[col4];
            a0.x += v0.x; a0.y += v0.y; a0.z += v0.z; a0.w += v0.w;
            a1.x += v1.x; a1.y += v1.y; a1.z += v1.z; a1.w += v1.w;
            a2.x += v2.x; a2.y += v2.y; a2.z += v2.z; a2.w += v2.w;
            a3.x += v3.x; a3.y += v3.y; a3.z += v3.z; a3.w += v3.w;
        }
        for (; i < cnt; i++) {
            int t0 = toks[i];
            float4 v0 = reinterpret_cast<const float4*>(h + (size_t)t0 * D_DIM)[col4];
            a0.x += v0.x; a0.y += v0.y; a0.z += v0.z; a0.w += v0.w;
        }
        float inv = 1.0f / (float)cnt;
        float sx = (a0.x + a1.x) + (a2.x + a3.x);
        float sy = (a0.y + a1.y) + (a2.y + a3.y);
        float sz = (a0.z + a1.z) + (a2.z + a3.z);
        float sw = (a0.w + a1.w) + (a2.w + a3.w);
        res.x = 0.1f * (sx * inv) + 0.9f * cur.x;
        res.y = 0.1f * (sy * inv) + 0.9f * cur.y;
        res.z = 0.1f * (sz * inv) + 0.9f * cur.z;
        res.w = 0.1f * (sw * inv) + 0.9f * cur.w;
    }
    reinterpret_cast<float4*>(out)[slot * (D_DIM / 4) + col4] = res;
}

// ---------------------------------------------------------------------------
extern "C" void kernel_launch(void* const* d_in, const int* in_sizes, int n_in,
                              void* d_out, int out_size) {
    const float* hidden = (const float*)d_in[0];   // [8192, 4096]
    const float* attn   = (const float*)d_in[1];   // [8192, 4]
    const float* memory = (const float*)d_in[2];   // [1, 128, 4096]
    const float* W      = (const float*)d_in[3];   // [1, 4096]
    const float* b      = (const float*)d_in[4];   // [1]
    const int*   slots  = (const int*)d_in[5];     // [8192, 4]
    float* out = (float*)d_out;                    // [1, 128, 4096]

    importance_partial_kernel<<<T_TOK, 256>>>(hidden, W);
    select_kernel<<<1, 1024>>>(slots, attn, b);
    aggregate_kernel<<<dim3(8, N_SLOTS), 128>>>(hidden, memory, out);
}

// round 11
// speedup vs baseline: 1.1546x; 1.0957x over previous
#include <cuda_runtime.h>
#include <math.h>

#define T_TOK 8192
#define D_DIM 4096
#define KS 4
#define N_SLOTS 128
#define TOPK 1024
#define MAX_ENTRIES 4096   // TOPK * KS worst case into one slot
#define NCHUNK 8           // 512-col chunks per token row

// ---------------- scratch (static device globals; no allocation) ----------
__device__ float        g_phh[T_TOK * NCHUNK];   // per-(token,chunk) sum h*h
__device__ float        g_phw[T_TOK * NCHUNK];   // per-(token,chunk) sum h*W
__device__ unsigned int g_keys[T_TOK];           // sortable importance keys
__device__ int          g_slot_cnt[N_SLOTS];
__device__ int          g_slot_tokens[N_SLOTS * MAX_ENTRIES];

// ---------------------------------------------------------------------------
// Kernel 1: barrier-free partial sums for importance (measured: 24.8us,
// occ 81%, DRAM 68%). Block = 1 token (8 warps); warp w owns cols [w*512,
// (w+1)*512). Warp shfl-reduce, lane 0 writes partials. No smem/barriers.
// ---------------------------------------------------------------------------
__global__ void __launch_bounds__(256, 7)
importance_partial_kernel(const float* __restrict__ h,
                          const float* __restrict__ W) {
    const int t = blockIdx.x;
    const int wid = threadIdx.x >> 5;       // chunk 0..7
    const int lane = threadIdx.x & 31;

    const float4* __restrict__ hr =
        reinterpret_cast<const float4*>(h + (size_t)t * D_DIM) + wid * 128;
    const float4* __restrict__ wr =
        reinterpret_cast<const float4*>(W) + wid * 128;

    float hh = 0.f, hw = 0.f;
#pragma unroll
    for (int qq = 0; qq < 4; qq += 2) {
        float4 a0 = __ldcs(&hr[lane + 32 * qq]);
        float4 a1 = __ldcs(&hr[lane + 32 * (qq + 1)]);
        float4 w0 = __ldg(&wr[lane + 32 * qq]);
        float4 w1 = __ldg(&wr[lane + 32 * (qq + 1)]);
        hh += a0.x * a0.x + a0.y * a0.y + a0.z * a0.z + a0.w * a0.w;
        hw += a0.x * w0.x + a0.y * w0.y + a0.z * w0.z + a0.w * w0.w;
        hh += a1.x * a1.x + a1.y * a1.y + a1.z * a1.z + a1.w * a1.w;
        hw += a1.x * w1.x + a1.y * w1.y + a1.z * w1.z + a1.w * w1.w;
    }
#pragma unroll
    for (int off = 16; off; off >>= 1) {
        hh += __shfl_xor_sync(0xFFFFFFFFu, hh, off);
        hw += __shfl_xor_sync(0xFFFFFFFFu, hw, off);
    }
    if (lane == 0) {
        __stcg(&g_phh[t * NCHUNK + wid], hh);
        __stcg(&g_phw[t * NCHUNK + wid], hw);
    }
}

// ---------------------------------------------------------------------------
// Kernel 1b: parallel finalize — one token per thread, 64 blocks across SMs.
// Reduces the 8 chunk-partials, applies the importance formula (MUFU), and
// writes the order-preserving sortable uint key. This work was previously
// folded into the single-SM select kernel (+4us); here it's ~1us parallel.
// ---------------------------------------------------------------------------
__global__ void finalize_kernel(const float* __restrict__ attn,
                                const float* __restrict__ b) {
    int t = blockIdx.x * blockDim.x + threadIdx.x;
    float bv = b[0];

    const float4* ph = reinterpret_cast<const float4*>(&g_phh[t * NCHUNK]);
    const float4* pw = reinterpret_cast<const float4*>(&g_phw[t * NCHUNK]);
    float4 h0 = ph[0], h1 = ph[1];
    float4 w0 = pw[0], w1 = pw[1];
    float hh = (h0.x + h0.y) + (h0.z + h0.w) + (h1.x + h1.y) + (h1.z + h1.w);
    float hw = (w0.x + w0.y) + (w0.z + w0.w) + (w1.x + w1.y) + (w1.z + w1.w);

    float mag = sqrtf(hh);
    float4 a4 = *reinterpret_cast<const float4*>(attn + t * 4);
    float ent = -(a4.x * __logf(a4.x + 1e-8f) + a4.y * __logf(a4.y + 1e-8f) +
                  a4.z * __logf(a4.z + 1e-8f) + a4.w * __logf(a4.w + 1e-8f));
    float surprise = ent * (1.0f / 1.3862943611198906f);   // / log(4)
    float learned = 1.0f / (1.0f + __expf(-(hw + bv)));
    float imp = mag * (1.0f + surprise) + learned;

    unsigned int u = __float_as_uint(imp);
    u ^= (u & 0x80000000u) ? 0xFFFFFFFFu : 0x80000000u;
    g_keys[t] = u;
}

// ---------------------------------------------------------------------------
// Kernel 2: exact top-1024 selection (R1 core verbatim — fastest measured)
// over precomputed keys + per-slot list build. Ties broken toward lowest
// index to match jax.lax.top_k's selected SET.
// ---------------------------------------------------------------------------
__global__ void select_kernel(const int* __restrict__ slot_indices) {
    __shared__ unsigned int su[T_TOK];   // 32 KB sortable keys
    __shared__ int hist[256];
    __shared__ int s_bucket, s_k, s_cnt;
    __shared__ int s_slot_cnt[N_SLOTS];

    int tid = threadIdx.x;

    // load precomputed keys
#pragma unroll
    for (int i = 0; i < 8; i++) {
        int t = tid + i * 1024;
        su[t] = g_keys[t];
    }
    __syncthreads();

    // 4-pass 8-bit radix select for the value v of the TOPK-th largest key
    unsigned int prefix = 0, kmask = 0;
    int k = TOPK;
    for (int shift = 24; shift >= 0; shift -= 8) {
        if (tid < 256) hist[tid] = 0;
        __syncthreads();
#pragma unroll
        for (int i = 0; i < 8; i++) {
            int t = tid + i * 1024;
            unsigned int u = su[t];
            if ((u & kmask) == prefix) atomicAdd(&hist[(u >> shift) & 255], 1);
        }
        __syncthreads();
        if (tid == 0) {
            int cum = 0, bsel = 0;
            for (int bb = 255; bb >= 0; bb--) {
                cum += hist[bb];
                if (cum >= k) { bsel = bb; s_k = k - (cum - hist[bb]); break; }
            }
            s_bucket = bsel;
        }
        __syncthreads();
        prefix |= ((unsigned int)s_bucket) << shift;
        kmask  |= 0xFFu << shift;
        k = s_k;
        __syncthreads();
    }
    unsigned int v = prefix;
    int r = k;   // need r elements among keys == v, taken at smallest indices

    // count ties
    if (tid == 0) s_cnt = 0;
    __syncthreads();
    {
        int c = 0;
#pragma unroll
        for (int i = 0; i < 8; i++) { int t = tid + i * 1024; c += (su[t] == v); }
        atomicAdd(&s_cnt, c);
    }
    __syncthreads();
    int m = s_cnt;

    // binary search index threshold X: smallest X with |{t < X : key==v}| >= r
    int X = T_TOK;
    if (r < m) {
        int lo = 0, hi = T_TOK;
        while (lo < hi) {
            int mid = (lo + hi) >> 1;
            __syncthreads();
            if (tid == 0) s_cnt = 0;
            __syncthreads();
            int c = 0;
#pragma unroll
            for (int i = 0; i < 8; i++) {
                int t = tid + i * 1024;
                c += (t < mid && su[t] == v);
            }
            atomicAdd(&s_cnt, c);
            __syncthreads();
            int got = s_cnt;
            __syncthreads();
            if (got >= r) hi = mid; else lo = mid + 1;
        }
        X = lo;
    }

    // build per-slot token lists
    if (tid < N_SLOTS) s_slot_cnt[tid] = 0;
    __syncthreads();
#pragma unroll
    for (int i = 0; i < 8; i++) {
        int t = tid + i * 1024;
        unsigned int u = su[t];
        if (u > v || (u == v && t < X)) {
            int4 s4 = *reinterpret_cast<const int4*>(slot_indices + t * KS);
            int s;
            s = s4.x; g_slot_tokens[s * MAX_ENTRIES + atomicAdd(&s_slot_cnt[s], 1)] = t;
            s = s4.y; g_slot_tokens[s * MAX_ENTRIES + atomicAdd(&s_slot_cnt[s], 1)] = t;
            s = s4.z; g_slot_tokens[s * MAX_ENTRIES + atomicAdd(&s_slot_cnt[s], 1)] = t;
            s = s4.w; g_slot_tokens[s * MAX_ENTRIES + atomicAdd(&s_slot_cnt[s], 1)] = t;
        }
    }
    __syncthreads();
    if (tid < N_SLOTS) g_slot_cnt[tid] = s_slot_cnt[tid];
}

// ---------------------------------------------------------------------------
// Kernel 3: per-slot gather-sum, mean, EMA write (R1 version verbatim).
// One block per (slot, 512-col chunk). 4-way unrolled gather.
// ---------------------------------------------------------------------------
__global__ void aggregate_kernel(const float* __restrict__ h,
                                 const float* __restrict__ mem,
                                 float* __restrict__ out) {
    int slot = blockIdx.y;
    int col4 = blockIdx.x * 128 + threadIdx.x;   // float4 index (0..1023)
    int cnt = g_slot_cnt[slot];

    const float4* cur_row = reinterpret_cast<const float4*>(mem + (size_t)slot * D_DIM);
    float4 cur = cur_row[col4];
    float4 res = cur;

    if (cnt > 0) {
        const int* toks = &g_slot_tokens[slot * MAX_ENTRIES];
        float4 a0 = {0, 0, 0, 0}, a1 = {0, 0, 0, 0}, a2 = {0, 0, 0, 0}, a3 = {0, 0, 0, 0};
        int i = 0;
        for (; i + 3 < cnt; i += 4) {
            int t0 = toks[i], t1 = toks[i + 1], t2 = toks[i + 2], t3 = toks[i + 3];
            float4 v0 = reinterpret_cast<const float4*>(h + (size_t)t0 * D_DIM)[col4];
            float4 v1 = reinterpret_cast<const float4*>(h + (size_t)t1 * D_DIM)[col4];
            float4 v2 = reinterpret_cast<const float4*>(h + (size_t)t2 * D_DIM)[col4];
            float4 v3 = reinterpret_cast<const float4*>(h + (size_t)t3 * D_DIM)[col4];
            a0.x += v0.x; a0.y += v0.y; a0.z += v0.z; a0.w += v0.w;
            a1.x += v1.x; a1.y += v1.y; a1.z += v1.z; a1.w += v1.w;
            a2.x += v2.x; a2.y += v2.y; a2.z += v2.z; a2.w += v2.w;
            a3.x += v3.x; a3.y += v3.y; a3.z += v3.z; a3.w += v3.w;
        }
        for (; i < cnt; i++) {
            int t0 = toks[i];
            float4 v0 = reinterpret_cast<const float4*>(h + (size_t)t0 * D_DIM)[col4];
            a0.x += v0.x; a0.y += v0.y; a0.z += v0.z; a0.w += v0.w;
        }
        float inv = 1.0f / (float)cnt;
        float sx = (a0.x + a1.x) + (a2.x + a3.x);
        float sy = (a0.y + a1.y) + (a2.y + a3.y);
        float sz = (a0.z + a1.z) + (a2.z + a3.z);
        float sw = (a0.w + a1.w) + (a2.w + a3.w);
        res.x = 0.1f * (sx * inv) + 0.9f * cur.x;
        res.y = 0.1f * (sy * inv) + 0.9f * cur.y;
        res.z = 0.1f * (sz * inv) + 0.9f * cur.z;
        res.w = 0.1f * (sw * inv) + 0.9f * cur.w;
    }
    reinterpret_cast<float4*>(out)[slot * (D_DIM / 4) + col4] = res;
}

// ---------------------------------------------------------------------------
extern "C" void kernel_launch(void* const* d_in, const int* in_sizes, int n_in,
                              void* d_out, int out_size) {
    const float* hidden = (const float*)d_in[0];   // [8192, 4096]
    const float* attn   = (const float*)d_in[1];   // [8192, 4]
    const float* memory = (const float*)d_in[2];   // [1, 128, 4096]
    const float* W      = (const float*)d_in[3];   // [1, 4096]
    const float* b      = (const float*)d_in[4];   // [1]
    const int*   slots  = (const int*)d_in[5];     // [8192, 4]
    float* out = (float*)d_out;                    // [1, 128, 4096]

    importance_partial_kernel<<<T_TOK, 256>>>(hidden, W);
    finalize_kernel<<<T_TOK / 128, 128>>>(attn, b);
    select_kernel<<<1, 1024>>>(slots);
    aggregate_kernel<<<dim3(8, N_SLOTS), 128>>>(hidden, memory, out);
}

// round 12
// speedup vs baseline: 1.2095x; 1.0475x over previous
#include <cuda_runtime.h>
#include <math.h>

#define T_TOK 8192
#define D_DIM 4096
#define KS 4
#define N_SLOTS 128
#define TOPK 1024
#define MAX_ENTRIES 4096   // TOPK * KS worst case into one slot
#define NCHUNK 8           // 512-col chunks per token row

// ---------------- scratch (static device globals; no allocation) ----------
__device__ float        g_phh[T_TOK * NCHUNK];   // per-(token,chunk) sum h*h
__device__ float        g_phw[T_TOK * NCHUNK];   // per-(token,chunk) sum h*W
__device__ unsigned int g_keys[T_TOK];           // sortable importance keys
__device__ int          g_slot_cnt[N_SLOTS];
__device__ int          g_slot_tokens[N_SLOTS * MAX_ENTRIES];

// ---------------------------------------------------------------------------
// Kernel 1: barrier-free partial sums for importance (measured: 24.8us,
// occ 81%, DRAM 68%). Block = 1 token (8 warps); warp w owns cols [w*512,
// (w+1)*512). Warp shfl-reduce, lane 0 writes partials. No smem/barriers.
// ---------------------------------------------------------------------------
__global__ void __launch_bounds__(256, 7)
importance_partial_kernel(const float* __restrict__ h,
                          const float* __restrict__ W) {
    const int t = blockIdx.x;
    const int wid = threadIdx.x >> 5;       // chunk 0..7
    const int lane = threadIdx.x & 31;

    const float4* __restrict__ hr =
        reinterpret_cast<const float4*>(h + (size_t)t * D_DIM) + wid * 128;
    const float4* __restrict__ wr =
        reinterpret_cast<const float4*>(W) + wid * 128;

    float hh = 0.f, hw = 0.f;
#pragma unroll
    for (int qq = 0; qq < 4; qq += 2) {
        float4 a0 = __ldcs(&hr[lane + 32 * qq]);
        float4 a1 = __ldcs(&hr[lane + 32 * (qq + 1)]);
        float4 w0 = __ldg(&wr[lane + 32 * qq]);
        float4 w1 = __ldg(&wr[lane + 32 * (qq + 1)]);
        hh += a0.x * a0.x + a0.y * a0.y + a0.z * a0.z + a0.w * a0.w;
        hw += a0.x * w0.x + a0.y * w0.y + a0.z * w0.z + a0.w * w0.w;
        hh += a1.x * a1.x + a1.y * a1.y + a1.z * a1.z + a1.w * a1.w;
        hw += a1.x * w1.x + a1.y * w1.y + a1.z * w1.z + a1.w * w1.w;
    }
#pragma unroll
    for (int off = 16; off; off >>= 1) {
        hh += __shfl_xor_sync(0xFFFFFFFFu, hh, off);
        hw += __shfl_xor_sync(0xFFFFFFFFu, hw, off);
    }
    if (lane == 0) {
        __stcg(&g_phh[t * NCHUNK + wid], hh);
        __stcg(&g_phw[t * NCHUNK + wid], hw);
    }
}

// ---------------------------------------------------------------------------
// Kernel 1b: parallel finalize — one token per thread across SMs. Reduces
// the 8 chunk-partials, applies the importance formula (MUFU), writes the
// order-preserving sortable uint key.
// ---------------------------------------------------------------------------
__global__ void finalize_kernel(const float* __restrict__ attn,
                                const float* __restrict__ b) {
    int t = blockIdx.x * blockDim.x + threadIdx.x;
    float bv = b[0];

    const float4* ph = reinterpret_cast<const float4*>(&g_phh[t * NCHUNK]);
    const float4* pw = reinterpret_cast<const float4*>(&g_phw[t * NCHUNK]);
    float4 h0 = ph[0], h1 = ph[1];
    float4 w0 = pw[0], w1 = pw[1];
    float hh = (h0.x + h0.y) + (h0.z + h0.w) + (h1.x + h1.y) + (h1.z + h1.w);
    float hw = (w0.x + w0.y) + (w0.z + w0.w) + (w1.x + w1.y) + (w1.z + w1.w);

    float mag = sqrtf(hh);
    float4 a4 = *reinterpret_cast<const float4*>(attn + t * 4);
    float ent = -(a4.x * __logf(a4.x + 1e-8f) + a4.y * __logf(a4.y + 1e-8f) +
                  a4.z * __logf(a4.z + 1e-8f) + a4.w * __logf(a4.w + 1e-8f));
    float surprise = ent * (1.0f / 1.3862943611198906f);   // / log(4)
    float learned = 1.0f / (1.0f + __expf(-(hw + bv)));
    float imp = mag * (1.0f + surprise) + learned;

    unsigned int u = __float_as_uint(imp);
    u ^= (u & 0x80000000u) ? 0xFFFFFFFFu : 0x80000000u;
    g_keys[t] = u;
}

// ---------------------------------------------------------------------------
// Kernel 2: exact top-1024 selection (R1 core verbatim — fastest measured)
// over precomputed keys + per-slot list build. Ties broken toward lowest
// index to match jax.lax.top_k's selected SET.
// ---------------------------------------------------------------------------
__global__ void select_kernel(const int* __restrict__ slot_indices) {
    __shared__ unsigned int su[T_TOK];   // 32 KB sortable keys
    __shared__ int hist[256];
    __shared__ int s_bucket, s_k, s_cnt;
    __shared__ int s_slot_cnt[N_SLOTS];

    int tid = threadIdx.x;

    // load precomputed keys
#pragma unroll
    for (int i = 0; i < 8; i++) {
        int t = tid + i * 1024;
        su[t] = g_keys[t];
    }
    __syncthreads();

    // 4-pass 8-bit radix select for the value v of the TOPK-th largest key
    unsigned int prefix = 0, kmask = 0;
    int k = TOPK;
    for (int shift = 24; shift >= 0; shift -= 8) {
        if (tid < 256) hist[tid] = 0;
        __syncthreads();
#pragma unroll
        for (int i = 0; i < 8; i++) {
            int t = tid + i * 1024;
            unsigned int u = su[t];
            if ((u & kmask) == prefix) atomicAdd(&hist[(u >> shift) & 255], 1);
        }
        __syncthreads();
        if (tid == 0) {
            int cum = 0, bsel = 0;
            for (int bb = 255; bb >= 0; bb--) {
                cum += hist[bb];
                if (cum >= k) { bsel = bb; s_k = k - (cum - hist[bb]); break; }
            }
            s_bucket = bsel;
        }
        __syncthreads();
        prefix |= ((unsigned int)s_bucket) << shift;
        kmask  |= 0xFFu << shift;
        k = s_k;
        __syncthreads();
    }
    unsigned int v = prefix;
    int r = k;   // need r elements among keys == v, taken at smallest indices

    // count ties
    if (tid == 0) s_cnt = 0;
    __syncthreads();
    {
        int c = 0;
#pragma unroll
        for (int i = 0; i < 8; i++) { int t = tid + i * 1024; c += (su[t] == v); }
        atomicAdd(&s_cnt, c);
    }
    __syncthreads();
    int m = s_cnt;

    // binary search index threshold X: smallest X with |{t < X : key==v}| >= r
    int X = T_TOK;
    if (r < m) {
        int lo = 0, hi = T_TOK;
        while (lo < hi) {
            int mid = (lo + hi) >> 1;
            __syncthreads();
            if (tid == 0) s_cnt = 0;
            __syncthreads();
            int c = 0;
#pragma unroll
            for (int i = 0; i < 8; i++) {
                int t = tid + i * 1024;
                c += (t < mid && su[t] == v);
            }
            atomicAdd(&s_cnt, c);
            __syncthreads();
            int got = s_cnt;
            __syncthreads();
            if (got >= r) hi = mid; else lo = mid + 1;
        }
        X = lo;
    }

    // build per-slot token lists
    if (tid < N_SLOTS) s_slot_cnt[tid] = 0;
    __syncthreads();
#pragma unroll
    for (int i = 0; i < 8; i++) {
        int t = tid + i * 1024;
        unsigned int u = su[t];
        if (u > v || (u == v && t < X)) {
            int4 s4 = *reinterpret_cast<const int4*>(slot_indices + t * KS);
            int s;
            s = s4.x; g_slot_tokens[s * MAX_ENTRIES + atomicAdd(&s_slot_cnt[s], 1)] = t;
            s = s4.y; g_slot_tokens[s * MAX_ENTRIES + atomicAdd(&s_slot_cnt[s], 1)] = t;
            s = s4.z; g_slot_tokens[s * MAX_ENTRIES + atomicAdd(&s_slot_cnt[s], 1)] = t;
            s = s4.w; g_slot_tokens[s * MAX_ENTRIES + atomicAdd(&s_slot_cnt[s], 1)] = t;
        }
    }
    __syncthreads();
    if (tid < N_SLOTS) g_slot_cnt[tid] = s_slot_cnt[tid];
}

// ---------------------------------------------------------------------------
// Kernel 3: per-slot gather-sum, mean, EMA write. One block per
// (slot, 512-col chunk). This round: token list staged into SMEM (kills the
// per-iteration dependent L2 load feeding gather addresses) + 8-way
// unrolled gather (MLP 8). Kernel is single-wave latency-bound (was
// DRAM 16%, issue 15%), so exposed-latency cuts translate ~1:1 to time.
// ---------------------------------------------------------------------------
__global__ void aggregate_kernel(const float* __restrict__ h,
                                 const float* __restrict__ mem,
                                 float* __restrict__ out) {
    __shared__ int s_toks[MAX_ENTRIES];
    int slot = blockIdx.y;
    int col4 = blockIdx.x * 128 + threadIdx.x;   // float4 index (0..1023)
    int cnt = g_slot_cnt[slot];

    // stage token list (coalesced)
    {
        const int* toks = &g_slot_tokens[slot * MAX_ENTRIES];
        for (int i = threadIdx.x; i < cnt; i += 128) s_toks[i] = toks[i];
    }

    const float4* cur_row = reinterpret_cast<const float4*>(mem + (size_t)slot * D_DIM);
    float4 cur = cur_row[col4];
    float4 res = cur;
    __syncthreads();

    if (cnt > 0) {
        float sx = 0.f, sy = 0.f, sz = 0.f, sw = 0.f;
        int i = 0;
        for (; i + 7 < cnt; i += 8) {
            float4 vv[8];
#pragma unroll
            for (int q = 0; q < 8; q++) {
                int tq = s_toks[i + q];
                vv[q] = __ldg(&reinterpret_cast<const float4*>(h + (size_t)tq * D_DIM)[col4]);
            }
#pragma unroll
            for (int q = 0; q < 8; q++) {
                sx += vv[q].x; sy += vv[q].y; sz += vv[q].z; sw += vv[q].w;
            }
        }
        for (; i < cnt; i++) {
            int tq = s_toks[i];
            float4 v0 = __ldg(&reinterpret_cast<const float4*>(h + (size_t)tq * D_DIM)[col4]);
            sx += v0.x; sy += v0.y; sz += v0.z; sw += v0.w;
        }
        float inv = 1.0f / (float)cnt;
        res.x = 0.1f * (sx * inv) + 0.9f * cur.x;
        res.y = 0.1f * (sy * inv) + 0.9f * cur.y;
        res.z = 0.1f * (sz * inv) + 0.9f * cur.z;
        res.w = 0.1f * (sw * inv) + 0.9f * cur.w;
    }
    reinterpret_cast<float4*>(out)[slot * (D_DIM / 4) + col4] = res;
}

// ---------------------------------------------------------------------------
extern "C" void kernel_launch(void* const* d_in, const int* in_sizes, int n_in,
                              void* d_out, int out_size) {
    const float* hidden = (const float*)d_in[0];   // [8192, 4096]
    const float* attn   = (const float*)d_in[1];   // [8192, 4]
    const float* memory = (const float*)d_in[2];   // [1, 128, 4096]
    const float* W      = (const float*)d_in[3];   // [1, 4096]
    const float* b      = (const float*)d_in[4];   // [1]
    const int*   slots  = (const int*)d_in[5];     // [8192, 4]
    float* out = (float*)d_out;                    // [1, 128, 4096]

    importance_partial_kernel<<<T_TOK, 256>>>(hidden, W);
    finalize_kernel<<<T_TOK / 128, 128>>>(attn, b);
    select_kernel<<<1, 1024>>>(slots);
    aggregate_kernel<<<dim3(8, N_SLOTS), 128>>>(hidden, memory, out);
}